// round 2
// baseline (speedup 1.0000x reference)
#include <cuda_runtime.h>
#include <cuda_bf16.h>
#include <math.h>

// Problem constants
#define BB 32
#define SS 256
#define EE 768
#define HH_ 12
#define DH 64
#define LL 2
#define FF_ 2048
#define MM (BB*SS)          // 8192 tokens
#define NEGV (-1e30f)
#define KEEP_HIST 64
#define KEEP_TGT 63

// ---------------- scratch (device globals; no allocation allowed) ----------------
__device__ float g_x[MM*EE];        // hidden state
__device__ float g_qkv[MM*3*EE];    // qkv projections
__device__ float g_attn[MM*EE];     // attention output / dense output reuse
__device__ float g_y[MM*EE];        // projection temp
__device__ float g_h[MM*FF_];       // FFN hidden
__device__ float g_sc[(size_t)BB*HH_*SS*SS]; // attention scores
__device__ float g_cos[MM];

// ---------------- reductions ----------------
__device__ __forceinline__ float warp_sum(float v) {
    #pragma unroll
    for (int o = 16; o; o >>= 1) v += __shfl_xor_sync(0xffffffffu, v, o);
    return v;
}
__device__ __forceinline__ float block_sum(float v, float* red) {
    int lane = threadIdx.x & 31, w = threadIdx.x >> 5;
    v = warp_sum(v);
    if (lane == 0) red[w] = v;
    __syncthreads();
    if (w == 0) {
        float x = (lane < (int)(blockDim.x >> 5)) ? red[lane] : 0.f;
        x = warp_sum(x);
        if (lane == 0) red[0] = x;
    }
    __syncthreads();
    float r = red[0];
    __syncthreads();
    return r;
}

// ==================================================================================
// TF32x3 tensor-core GEMM:  C[M,N] = A[M,K] @ W[N,K]^T + bias   (exactly fp32-class)
// Each fp32 x is split x = hi + lo (both tf32); product uses Ah*Bh + Ah*Bl + Al*Bh.
// Block tile 128x256xK16, 8 warps each 64x64, mma.sync.m16n8k8.tf32.
// EPI: 0 none, 1 relu, 2 tanh
// ==================================================================================

#define MMA_TF32(c, a, b) asm volatile( \
    "mma.sync.aligned.m16n8k8.row.col.f32.tf32.tf32.f32 " \
    "{%0,%1,%2,%3},{%4,%5,%6,%7},{%8,%9},{%0,%1,%2,%3};" \
    : "+f"((c)[0]), "+f"((c)[1]), "+f"((c)[2]), "+f"((c)[3]) \
    : "r"((a)[0]), "r"((a)[1]), "r"((a)[2]), "r"((a)[3]), \
      "r"((b)[0]), "r"((b)[1]))

__device__ __forceinline__ unsigned cvt_tf32(float x) {
    unsigned u; asm("cvt.rna.tf32.f32 %0, %1;" : "=r"(u) : "f"(x)); return u;
}

template<int EPI>
__global__ __launch_bounds__(256) void gemm_tf32x3(
    const float* __restrict__ A, const float* __restrict__ W,
    const float* __restrict__ bias, float* __restrict__ C,
    int M, int N, int K)
{
    extern __shared__ float2 sm2[];
    float2* As = sm2;                 // [2][16][128] (k-major, hi/lo pairs, XOR-swizzled m)
    float2* Bs = sm2 + 2*16*128;      // [2][16][256]

    const int tid  = threadIdx.x;
    const int lane = tid & 31, warp = tid >> 5;
    const int wm = warp & 1, wn = warp >> 1;   // 2 x 4 warp grid
    const int tig = lane & 3, gid = lane >> 2;

    const int m_blk = blockIdx.y * 128;
    const int n_blk = blockIdx.x * 256;

    const int lr = tid >> 2;          // 0..63 : row within tile slab
    const int lc = tid & 3;           // 0..3  : k-chunk (float4)

    float4 pa[2], pb[4];
    float acc[4][8][4];
    #pragma unroll
    for (int i = 0; i < 4; i++)
        #pragma unroll
        for (int j = 0; j < 8; j++)
            #pragma unroll
            for (int q = 0; q < 4; q++) acc[i][j][q] = 0.f;

    const int KT = K >> 4;

    auto ld_tiles = [&](int kt) {
        const float* Ap = A + (size_t)(m_blk + lr) * K + kt * 16 + lc * 4;
        pa[0] = *(const float4*)(Ap);
        pa[1] = *(const float4*)(Ap + (size_t)64 * K);
        const float* Wp = W + (size_t)(n_blk + lr) * K + kt * 16 + lc * 4;
        #pragma unroll
        for (int i = 0; i < 4; i++)
            pb[i] = *(const float4*)(Wp + (size_t)(i * 64) * K);
    };

    auto st_tiles = [&](int buf) {
        #pragma unroll
        for (int i = 0; i < 2; i++) {
            int m = lr + i * 64;
            float vals[4] = {pa[i].x, pa[i].y, pa[i].z, pa[i].w};
            #pragma unroll
            for (int j = 0; j < 4; j++) {
                int k = lc * 4 + j;
                unsigned hi = cvt_tf32(vals[j]);
                unsigned lo = cvt_tf32(vals[j] - __uint_as_float(hi));
                As[(buf * 16 + k) * 128 + (m ^ (lc << 3))] =
                    make_float2(__uint_as_float(hi), __uint_as_float(lo));
            }
        }
        #pragma unroll
        for (int i = 0; i < 4; i++) {
            int n = lr + i * 64;
            float vals[4] = {pb[i].x, pb[i].y, pb[i].z, pb[i].w};
            #pragma unroll
            for (int j = 0; j < 4; j++) {
                int k = lc * 4 + j;
                unsigned hi = cvt_tf32(vals[j]);
                unsigned lo = cvt_tf32(vals[j] - __uint_as_float(hi));
                Bs[(buf * 16 + k) * 256 + (n ^ (lc << 3))] =
                    make_float2(__uint_as_float(hi), __uint_as_float(lo));
            }
        }
    };

    auto compute = [&](int buf) {
        #pragma unroll
        for (int kb = 0; kb < 16; kb += 8) {
            const int s0 = (kb >> 2) << 3;   // swizzle for rows kb+tig   (kb/4)<<3
            const int s1 = s0 + 8;           // swizzle for rows kb+tig+4
            unsigned ah[4][4], al[4][4];
            #pragma unroll
            for (int i = 0; i < 4; i++) {
                int m = wm * 64 + i * 16 + gid;
                float2 v0 = As[(buf * 16 + kb + tig)     * 128 + ( m      ^ s0)];
                float2 v1 = As[(buf * 16 + kb + tig)     * 128 + ((m + 8) ^ s0)];
                float2 v2 = As[(buf * 16 + kb + tig + 4) * 128 + ( m      ^ s1)];
                float2 v3 = As[(buf * 16 + kb + tig + 4) * 128 + ((m + 8) ^ s1)];
                ah[i][0] = __float_as_uint(v0.x); al[i][0] = __float_as_uint(v0.y);
                ah[i][1] = __float_as_uint(v1.x); al[i][1] = __float_as_uint(v1.y);
                ah[i][2] = __float_as_uint(v2.x); al[i][2] = __float_as_uint(v2.y);
                ah[i][3] = __float_as_uint(v3.x); al[i][3] = __float_as_uint(v3.y);
            }
            #pragma unroll
            for (int jh = 0; jh < 2; jh++) {
                unsigned bh[4][2], bl[4][2];
                #pragma unroll
                for (int j = 0; j < 4; j++) {
                    int n = wn * 64 + (jh * 4 + j) * 8 + gid;
                    float2 w0 = Bs[(buf * 16 + kb + tig)     * 256 + (n ^ s0)];
                    float2 w1 = Bs[(buf * 16 + kb + tig + 4) * 256 + (n ^ s1)];
                    bh[j][0] = __float_as_uint(w0.x); bl[j][0] = __float_as_uint(w0.y);
                    bh[j][1] = __float_as_uint(w1.x); bl[j][1] = __float_as_uint(w1.y);
                }
                #pragma unroll
                for (int i = 0; i < 4; i++)
                    #pragma unroll
                    for (int j = 0; j < 4; j++) {
                        float* c = acc[i][jh * 4 + j];
                        MMA_TF32(c, ah[i], bh[j]);
                        MMA_TF32(c, ah[i], bl[j]);
                        MMA_TF32(c, al[i], bh[j]);
                    }
            }
        }
    };

    ld_tiles(0);
    st_tiles(0);
    __syncthreads();
    for (int kt = 0; kt < KT; kt++) {
        if (kt + 1 < KT) ld_tiles(kt + 1);
        compute(kt & 1);
        if (kt + 1 < KT) st_tiles((kt + 1) & 1);
        __syncthreads();
    }

    // epilogue
    #pragma unroll
    for (int i = 0; i < 4; i++) {
        int row = m_blk + wm * 64 + i * 16 + gid;
        #pragma unroll
        for (int j = 0; j < 8; j++) {
            int col = n_blk + wn * 64 + j * 8 + tig * 2;
            float b0 = bias[col], b1 = bias[col + 1];
            float v0 = acc[i][j][0] + b0, v1 = acc[i][j][1] + b1;
            float v2 = acc[i][j][2] + b0, v3 = acc[i][j][3] + b1;
            if (EPI == 1) {
                v0 = fmaxf(v0, 0.f); v1 = fmaxf(v1, 0.f);
                v2 = fmaxf(v2, 0.f); v3 = fmaxf(v3, 0.f);
            }
            if (EPI == 2) {
                v0 = tanhf(v0); v1 = tanhf(v1);
                v2 = tanhf(v2); v3 = tanhf(v3);
            }
            *(float2*)(C + (size_t)row * N + col)       = make_float2(v0, v1);
            *(float2*)(C + (size_t)(row + 8) * N + col) = make_float2(v2, v3);
        }
    }
}

// ---------------- generic tiled FFMA GEMM (attention score / PV only) ----------------
// TB : 0 -> C[m,n] = sum_k A[m,k] * B[n*ldb + k]   (B is [N,K], "NT")
//      1 -> C[m,n] = sum_k A[m,k] * B[k*ldb + n]   (B is [K,N], "NN")
template<int EPI, int TB>
__global__ __launch_bounds__(256) void gemm_k(
    const float* __restrict__ A, const float* __restrict__ Bm,
    const float* __restrict__ bias, float* __restrict__ C,
    int M, int N, int K, int lda, int ldb, int ldc,
    long long saO, long long saI, long long sbO, long long sbI,
    long long scO, long long scI, int HHd)
{
    __shared__ __align__(16) float As[16][64];
    __shared__ __align__(16) float Bs[16][64];

    int z  = blockIdx.z;
    int zo = z / HHd, zi = z - zo * HHd;
    A  += zo * saO + zi * saI;
    Bm += zo * sbO + zi * sbI;
    C  += zo * scO + zi * scI;

    int tid = threadIdx.x;
    int tx = tid & 15, ty = tid >> 4;
    int m0 = blockIdx.y * 64, n0 = blockIdx.x * 64;
    int lr = tid >> 2, lc = (tid & 3) << 2;
    int br = tid >> 4, bc = (tid & 15) << 2;

    float acc[4][4] = {};

    for (int k0 = 0; k0 < K; k0 += 16) {
        float4 av = *(const float4*)(A + (size_t)(m0 + lr) * lda + k0 + lc);
        As[lc + 0][lr] = av.x; As[lc + 1][lr] = av.y;
        As[lc + 2][lr] = av.z; As[lc + 3][lr] = av.w;
        if (TB == 0) {
            float4 bv = *(const float4*)(Bm + (size_t)(n0 + lr) * ldb + k0 + lc);
            Bs[lc + 0][lr] = bv.x; Bs[lc + 1][lr] = bv.y;
            Bs[lc + 2][lr] = bv.z; Bs[lc + 3][lr] = bv.w;
        } else {
            float4 bv = *(const float4*)(Bm + (size_t)(k0 + br) * ldb + n0 + bc);
            *(float4*)&Bs[br][bc] = bv;
        }
        __syncthreads();
        #pragma unroll
        for (int kk = 0; kk < 16; kk++) {
            float4 a = *(const float4*)&As[kk][ty << 2];
            float4 b = *(const float4*)&Bs[kk][tx << 2];
            acc[0][0] += a.x * b.x; acc[0][1] += a.x * b.y; acc[0][2] += a.x * b.z; acc[0][3] += a.x * b.w;
            acc[1][0] += a.y * b.x; acc[1][1] += a.y * b.y; acc[1][2] += a.y * b.z; acc[1][3] += a.y * b.w;
            acc[2][0] += a.z * b.x; acc[2][1] += a.z * b.y; acc[2][2] += a.z * b.z; acc[2][3] += a.z * b.w;
            acc[3][0] += a.w * b.x; acc[3][1] += a.w * b.y; acc[3][2] += a.w * b.z; acc[3][3] += a.w * b.w;
        }
        __syncthreads();
    }

    float4 bb = make_float4(0.f, 0.f, 0.f, 0.f);
    if (bias) bb = *(const float4*)(bias + n0 + (tx << 2));
    #pragma unroll
    for (int i = 0; i < 4; i++) {
        int row = m0 + (ty << 2) + i;
        float4 v;
        v.x = acc[i][0] + bb.x; v.y = acc[i][1] + bb.y;
        v.z = acc[i][2] + bb.z; v.w = acc[i][3] + bb.w;
        if (EPI == 1) { v.x = fmaxf(v.x, 0.f); v.y = fmaxf(v.y, 0.f); v.z = fmaxf(v.z, 0.f); v.w = fmaxf(v.w, 0.f); }
        if (EPI == 2) { v.x = tanhf(v.x); v.y = tanhf(v.y); v.z = tanhf(v.z); v.w = tanhf(v.w); }
        *(float4*)(C + (size_t)row * ldc + n0 + (tx << 2)) = v;
    }
}

// ---------------- embed + LN ----------------
__global__ __launch_bounds__(256) void embed_ln_k(
    const float* __restrict__ tok, const int* __restrict__ pos,
    const int* __restrict__ typ, const float* __restrict__ pe,
    const float* __restrict__ temb, const float* __restrict__ w,
    const float* __restrict__ b, float* __restrict__ out)
{
    __shared__ float red[32];
    int t = blockIdx.x;
    int p = pos[t], ty = typ[t];
    int e0 = threadIdx.x;
    float v[3];
    #pragma unroll
    for (int i = 0; i < 3; i++) {
        int e = e0 + i * 256;
        v[i] = tok[(size_t)t * EE + e] + pe[(size_t)p * EE + e] + temb[(size_t)ty * EE + e];
    }
    float mean = block_sum(v[0] + v[1] + v[2], red) * (1.f / 768.f);
    float d[3]; float ss = 0.f;
    #pragma unroll
    for (int i = 0; i < 3; i++) { d[i] = v[i] - mean; ss += d[i] * d[i]; }
    float var = block_sum(ss, red) * (1.f / 768.f);
    float inv = rsqrtf(var + 1e-5f);
    #pragma unroll
    for (int i = 0; i < 3; i++) {
        int e = e0 + i * 256;
        out[(size_t)t * EE + e] = d[i] * inv * w[e] + b[e];
    }
}

// ---------------- (x + r) -> LN ----------------
__global__ __launch_bounds__(256) void add_ln_k(
    const float* __restrict__ x, const float* __restrict__ r,
    const float* __restrict__ w, const float* __restrict__ b,
    float* __restrict__ out)
{
    __shared__ float red[32];
    int t = blockIdx.x;
    int e0 = threadIdx.x;
    float v[3];
    #pragma unroll
    for (int i = 0; i < 3; i++) {
        int e = e0 + i * 256;
        float xv = x[(size_t)t * EE + e];
        if (r) xv += r[(size_t)t * EE + e];
        v[i] = xv;
    }
    float mean = block_sum(v[0] + v[1] + v[2], red) * (1.f / 768.f);
    float d[3]; float ss = 0.f;
    #pragma unroll
    for (int i = 0; i < 3; i++) { d[i] = v[i] - mean; ss += d[i] * d[i]; }
    float var = block_sum(ss, red) * (1.f / 768.f);
    float inv = rsqrtf(var + 1e-5f);
    #pragma unroll
    for (int i = 0; i < 3; i++) {
        int e = e0 + i * 256;
        out[(size_t)t * EE + e] = d[i] * inv * w[e] + b[e];
    }
}

// ---------------- masked softmax over score rows ----------------
__global__ __launch_bounds__(256) void softmax_k(
    float* __restrict__ sc, const unsigned char* __restrict__ mask)
{
    int w = threadIdx.x >> 5, lane = threadIdx.x & 31;
    long long r = (long long)blockIdx.x * 8 + w;
    int bh = (int)(r >> 8);
    int b = bh / HH_;
    float* row = sc + r * SS;
    const unsigned char* mrow = mask + (size_t)b * SS;
    float v[8];
    #pragma unroll
    for (int j = 0; j < 8; j++) {
        int k = lane + 32 * j;
        float x = row[k] * 0.125f;           // 1/sqrt(64)
        v[j] = mrow[k] ? NEGV : x;
    }
    float m = v[0];
    #pragma unroll
    for (int j = 1; j < 8; j++) m = fmaxf(m, v[j]);
    #pragma unroll
    for (int o = 16; o; o >>= 1) m = fmaxf(m, __shfl_xor_sync(0xffffffffu, m, o));
    float sum = 0.f;
    #pragma unroll
    for (int j = 0; j < 8; j++) { v[j] = __expf(v[j] - m); sum += v[j]; }
    sum = warp_sum(sum);
    float inv = 1.f / sum;
    #pragma unroll
    for (int j = 0; j < 8; j++) row[lane + 32 * j] = v[j] * inv;
}

// ---------------- cosine similarity per token ----------------
__global__ __launch_bounds__(256) void cos_k(
    const float* __restrict__ a, const float* __restrict__ bten, float* __restrict__ out)
{
    int w = threadIdx.x >> 5, lane = threadIdx.x & 31;
    int t = blockIdx.x * 8 + w;
    const float* pa = a + (size_t)t * EE;
    const float* pb = bten + (size_t)t * EE;
    float dot = 0.f, na = 0.f, nb = 0.f;
    for (int i = lane; i < EE; i += 32) {
        float x = pa[i], y = pb[i];
        dot += x * y; na += x * x; nb += y * y;
    }
    dot = warp_sum(dot); na = warp_sum(na); nb = warp_sum(nb);
    if (lane == 0)
        out[t] = dot / fmaxf(sqrtf(na) * sqrtf(nb), 1e-8f);
}

// ---------------- gumbel top-k mask generation ----------------
__global__ __launch_bounds__(256) void maskgen_k(
    const float* __restrict__ cosv, const int* __restrict__ typ,
    const float* __restrict__ gh, const float* __restrict__ gt,
    float* __restrict__ out)
{
    __shared__ float glh[256], glt[256];
    __shared__ float red[32];
    int b = blockIdx.x, s = threadIdx.x;
    int t = typ[b * SS + s];
    float c = cosv[b * SS + s];
    bool hm = (t == 1), tm = (t == 2);
    float eh = hm ? expf(c) : 0.f;
    float et = tm ? expf(c) : 0.f;
    float sh = block_sum(eh, red);
    float st = block_sum(et, red);
    float vh = hm ? (logf(eh / sh) + gh[b * SS + s]) : NEGV;
    float vt = tm ? (logf(1.f - et / st) + gt[b * SS + s]) : NEGV;
    glh[s] = vh; glt[s] = vt;
    __syncthreads();
    int rh = 0, rt = 0;
    for (int j = 0; j < 256; j++) {
        float a = glh[j];
        rh += (a > vh) || (a == vh && j < s);
        float bb2 = glt[j];
        rt += (bb2 > vt) || (bb2 == vt && j < s);
    }
    float o = 0.f;
    if (hm && rh < KEEP_HIST) o += 1.f;
    if (tm && rt < KEEP_TGT)  o += 1.f;
    out[b * SS + s] = o;
}

// ---------------- host launch ----------------
extern "C" void kernel_launch(void* const* d_in, const int* in_sizes, int n_in,
                              void* d_out, int out_size)
{
    const float* tok  = (const float*)d_in[0];
    const unsigned char* amask = (const unsigned char*)d_in[1];
    const int* pos    = (const int*)d_in[2];
    const int* typ    = (const int*)d_in[3];
    const float* gh   = (const float*)d_in[4];
    const float* gt   = (const float*)d_in[5];
    const float* pe   = (const float*)d_in[6];
    const float* temb = (const float*)d_in[7];
    const float* ln_w = (const float*)d_in[8];
    const float* ln_b = (const float*)d_in[9];
    const float* dense_w = (const float*)d_in[10];
    const float* dense_b = (const float*)d_in[11];
    const float* qkv_w = (const float*)d_in[12];
    const float* qkv_b = (const float*)d_in[13];
    const float* out_w = (const float*)d_in[14];
    const float* out_b = (const float*)d_in[15];
    const float* ln1_w = (const float*)d_in[16];
    const float* ln1_b = (const float*)d_in[17];
    const float* lin1_w = (const float*)d_in[18];
    const float* lin1_b = (const float*)d_in[19];
    const float* lin2_w = (const float*)d_in[20];
    const float* lin2_b = (const float*)d_in[21];
    const float* ln2_w = (const float*)d_in[22];
    const float* ln2_b = (const float*)d_in[23];
    float* out = (float*)d_out;

    float *gx, *gqkv, *gattn, *gy, *ghid, *gsc, *gcos;
    cudaGetSymbolAddress((void**)&gx,    g_x);
    cudaGetSymbolAddress((void**)&gqkv,  g_qkv);
    cudaGetSymbolAddress((void**)&gattn, g_attn);
    cudaGetSymbolAddress((void**)&gy,    g_y);
    cudaGetSymbolAddress((void**)&ghid,  g_h);
    cudaGetSymbolAddress((void**)&gsc,   g_sc);
    cudaGetSymbolAddress((void**)&gcos,  g_cos);

    const int SMEMSZ = 98304;   // 96 KB dynamic smem for tf32 kernel
    cudaFuncSetAttribute(gemm_tf32x3<0>, cudaFuncAttributeMaxDynamicSharedMemorySize, SMEMSZ);
    cudaFuncSetAttribute(gemm_tf32x3<1>, cudaFuncAttributeMaxDynamicSharedMemorySize, SMEMSZ);
    cudaFuncSetAttribute(gemm_tf32x3<2>, cudaFuncAttributeMaxDynamicSharedMemorySize, SMEMSZ);

    embed_ln_k<<<MM, 256>>>(tok, pos, typ, pe, temb, ln_w, ln_b, gx);

    for (int l = 0; l < LL; l++) {
        // qkv = x @ qkv_w[l]^T + qkv_b[l]      (M=8192, N=2304, K=768)
        gemm_tf32x3<0><<<dim3(9, 64), 256, SMEMSZ>>>(
            gx, qkv_w + (size_t)l * 3 * EE * EE, qkv_b + (size_t)l * 3 * EE, gqkv,
            MM, 3 * EE, EE);

        // scores[b,h,q,k] = q . k  (batched NT, z = b*H + h)
        gemm_k<0,0><<<dim3(4, 4, BB * HH_), 256>>>(
            gqkv, gqkv + EE, nullptr, gsc,
            SS, SS, DH, 3 * EE, 3 * EE, SS,
            (long long)SS * 3 * EE, DH,
            (long long)SS * 3 * EE, DH,
            (long long)HH_ * SS * SS, (long long)SS * SS, HH_);

        softmax_k<<<(BB * HH_ * SS) / 8, 256>>>(gsc, amask);

        // o[b,q,h,d] = P @ V (batched NN)
        gemm_k<0,1><<<dim3(1, 4, BB * HH_), 256>>>(
            gsc, gqkv + 2 * EE, nullptr, gattn,
            SS, DH, SS, SS, 3 * EE, EE,
            (long long)HH_ * SS * SS, (long long)SS * SS,
            (long long)SS * 3 * EE, DH,
            (long long)SS * EE, DH, HH_);

        // out proj (M=8192, N=768, K=768)
        gemm_tf32x3<0><<<dim3(3, 64), 256, SMEMSZ>>>(
            gattn, out_w + (size_t)l * EE * EE, out_b + (size_t)l * EE, gy,
            MM, EE, EE);

        add_ln_k<<<MM, 256>>>(gx, gy, ln1_w + l * EE, ln1_b + l * EE, gx);

        // FFN1 (M=8192, N=2048, K=768) + relu
        gemm_tf32x3<1><<<dim3(8, 64), 256, SMEMSZ>>>(
            gx, lin1_w + (size_t)l * FF_ * EE, lin1_b + (size_t)l * FF_, ghid,
            MM, FF_, EE);

        // FFN2 (M=8192, N=768, K=2048)
        gemm_tf32x3<0><<<dim3(3, 64), 256, SMEMSZ>>>(
            ghid, lin2_w + (size_t)l * EE * FF_, lin2_b + (size_t)l * EE, gy,
            MM, EE, FF_);

        add_ln_k<<<MM, 256>>>(gx, gy, ln2_w + l * EE, ln2_b + l * EE, gx);
    }

    // final LN (no residual)
    add_ln_k<<<MM, 256>>>(gx, nullptr, ln_w, ln_b, gy);

    // dense + tanh  (M=8192, N=768, K=768)
    gemm_tf32x3<2><<<dim3(3, 64), 256, SMEMSZ>>>(
        gy, dense_w, dense_b, gattn,
        MM, EE, EE);

    cos_k<<<MM / 8, 256>>>(tok, gattn, gcos);

    maskgen_k<<<BB, 256>>>(gcos, typ, gh, gt, out);
}